// round 12
// baseline (speedup 1.0000x reference)
#include <cuda_runtime.h>
#include <cstdint>

// celerite GP factor + solve + loglike. N=262144, J=16, R=4.
// Lane-split layout: 16 lanes per chunk, TWO chunks per warp (lane halves).
// Mid-loop reload: next-iter loads issue right after current rows are
// consumed, covered by the shfl/rank-1 tail (no extra prefetch registers).

#define JDIM 16
#define RDIM 4
#define OV   10
#define NMAX 262144
#define MAXC 16384
#define FULLM 0xffffffffu

typedef unsigned long long u64t;

__device__ float g_W[(size_t)NMAX * JDIM];
__device__ float g_z[(size_t)NMAX * RDIM];
__device__ float g_logd[MAXC];
__device__ float g_yx[MAXC * RDIM];

__device__ __forceinline__ float fast_rcp(float x) {
    float r;
    asm("rcp.approx.f32 %0, %1;" : "=f"(r) : "f"(x));
    r = r * (2.0f - x * r);
    return r;
}
__device__ __forceinline__ u64t pk2(float lo, float hi) {
    u64t r; asm("mov.b64 %0, {%1,%2};" : "=l"(r) : "f"(lo), "f"(hi)); return r;
}
__device__ __forceinline__ void upk2(u64t v, float& lo, float& hi) {
    asm("mov.b64 {%0,%1}, %2;" : "=f"(lo), "=f"(hi) : "l"(v));
}
__device__ __forceinline__ u64t mul2(u64t a, u64t b) {
    u64t r; asm("mul.rn.f32x2 %0, %1, %2;" : "=l"(r) : "l"(a), "l"(b)); return r;
}
__device__ __forceinline__ u64t add2(u64t a, u64t b) {
    u64t r; asm("add.rn.f32x2 %0, %1, %2;" : "=l"(r) : "l"(a), "l"(b)); return r;
}
__device__ __forceinline__ u64t fma2(u64t a, u64t b, u64t c) {
    u64t r; asm("fma.rn.f32x2 %0, %1, %2, %3;" : "=l"(r) : "l"(a), "l"(b), "l"(c)); return r;
}

// ---------------------------------------------------------------------------
// Kernel 1: fused factorization + forward solve. 2 chunks/warp (lane halves).
// Lane i of each half holds full S row i (8 packed f32x2) and F[i][0..4).
// ---------------------------------------------------------------------------
__global__ void __launch_bounds__(256, 3)
factor_forward_kernel(const float* __restrict__ a, const float* __restrict__ U,
                      const float* __restrict__ V, const float* __restrict__ P,
                      const float* __restrict__ y, int N, int C, int L)
{
    int warp = (blockIdx.x * blockDim.x + threadIdx.x) >> 5;
    int lane = threadIdx.x & 31;
    int il  = lane & 15;
    int b16 = lane & 16;
    int half = lane >> 4;

    int chunk = 2 * warp + half;
    bool active = (chunk < C) && ((size_t)chunk * L < (size_t)N);
    int s = active ? chunk * L : 0;
    int e = min(s + L, N);
    int m0 = max(0, s - OV);
    int len = active ? (e - m0 - 1) : 0;
    int w0 = s - m0 - 1;                 // first stored iteration (may be -1)
    int T = max(len, __shfl_xor_sync(FULLM, len, 16));

    // ---- init at row m0
    u64t S8[8];
    u64t fA, fB, zpA, zpB, wprevP;
    float llogd = 0.f;
    {
        float an = a[m0];
        float vi = V[(size_t)m0 * JDIM + il];
        float rd = fast_rcp(an);
        float wi = vi * rd;
        float wj[16];
#pragma unroll
        for (int j = 0; j < 16; j++) wj[j] = __shfl_sync(FULLM, wi, b16 + j);
        float dw = an * wi;
#pragma unroll
        for (int k = 0; k < 8; k++) S8[k] = pk2(dw * wj[2*k], dw * wj[2*k+1]);

        float4 y0 = *(const float4*)(y + (size_t)m0 * RDIM);
        zpA = pk2(y0.x, y0.y);
        zpB = pk2(y0.z, y0.w);
        fA = 0ull; fB = 0ull;
        wprevP = pk2(wi, wi);

        if (active && m0 == s) {   // chunk 0: store row 0
            g_W[(size_t)m0 * JDIM + il] = wi;
            if (il == 0) *(float4*)(g_z + (size_t)m0 * RDIM) =
                make_float4(y0.x * rd, y0.y * rd, y0.z * rd, y0.w * rd);
            llogd = __logf(an);
        }
    }

    // ---- pointers at first loop row n = m0+1 (P uses row n-1)
    int r1 = m0 + 1;
    const float* pP  = P + (size_t)m0 * JDIM;
    const float* pPi = pP + il;
    const float* pU  = U + (size_t)r1 * JDIM;
    const float* pUi = pU + il;
    const float* pVi = V + (size_t)r1 * JDIM + il;
    const float* pa  = a + r1;
    const float* pY  = y + (size_t)r1 * RDIM;
    float* pgW = g_W + (size_t)r1 * JDIM + il;
    float* pgz = g_z + (size_t)r1 * RDIM;

    // ---- preload first iteration
    ulonglong2 pjA = *(const ulonglong2*)(pP);
    ulonglong2 pjB = *(const ulonglong2*)(pP + 4);
    ulonglong2 pjC = *(const ulonglong2*)(pP + 8);
    ulonglong2 pjD = *(const ulonglong2*)(pP + 12);
    float pi = *pPi;
    ulonglong2 ujA = *(const ulonglong2*)(pU);
    ulonglong2 ujB = *(const ulonglong2*)(pU + 4);
    ulonglong2 ujC = *(const ulonglong2*)(pU + 8);
    ulonglong2 ujD = *(const ulonglong2*)(pU + 12);
    float ui = *pUi;
    float vi = *pVi;
    float an = *pa;
    float4 yv = *(const float4*)(pY);

#pragma unroll 1
    for (int t = 0; t < T; t++) {
        u64t pis = pk2(pi, pi);

        // F recurrence (consumes pi)
        fA = mul2(pis, fma2(wprevP, zpA, fA));
        fB = mul2(pis, fma2(wprevP, zpB, fB));

        // S decay (consumes pj*)
        S8[0] = mul2(S8[0], mul2(pis, pjA.x));
        S8[1] = mul2(S8[1], mul2(pis, pjA.y));
        S8[2] = mul2(S8[2], mul2(pis, pjB.x));
        S8[3] = mul2(S8[3], mul2(pis, pjB.y));
        S8[4] = mul2(S8[4], mul2(pis, pjC.x));
        S8[5] = mul2(S8[5], mul2(pis, pjC.y));
        S8[6] = mul2(S8[6], mul2(pis, pjD.x));
        S8[7] = mul2(S8[7], mul2(pis, pjD.y));

        // su_i = S row . U row (consumes uj*)
        u64t q0 = mul2(S8[0], ujA.x), q1 = mul2(S8[1], ujA.y);
        u64t q2 = mul2(S8[2], ujB.x), q3 = mul2(S8[3], ujB.y);
        u64t q4 = mul2(S8[4], ujC.x), q5 = mul2(S8[5], ujC.y);
        u64t q6 = mul2(S8[6], ujD.x), q7 = mul2(S8[7], ujD.y);
        u64t qa = add2(add2(q0, q1), add2(q2, q3));
        u64t qb = add2(add2(q4, q5), add2(q6, q7));
        float qlo, qhi; upk2(add2(qa, qb), qlo, qhi);
        float su = qlo + qhi;

        // save scalars still needed after the reload
        float ui_c = ui, vi_c = vi, an_c = an;
        float4 yv_c = yv;

        // ---- mid-loop reload for next iteration (frozen on tail) ----
        bool adv = (t + 1 < len);
        int d16 = adv ? JDIM : 0;
        int d4  = adv ? RDIM : 0;
        pP += d16; pPi += d16; pU += d16; pUi += d16; pVi += d16;
        pa += (d16 >> 4); pY += d4;
        pjA = *(const ulonglong2*)(pP);
        pjB = *(const ulonglong2*)(pP + 4);
        pjC = *(const ulonglong2*)(pP + 8);
        pjD = *(const ulonglong2*)(pP + 12);
        pi  = *pPi;
        ujA = *(const ulonglong2*)(pU);
        ujB = *(const ulonglong2*)(pU + 4);
        ujC = *(const ulonglong2*)(pU + 8);
        ujD = *(const ulonglong2*)(pU + 12);
        ui  = *pUi;
        vi  = *pVi;
        an  = *pa;
        yv  = *(const float4*)(pY);
        // -------------------------------------------------------------

        // reductions over the 16-lane half
        float fl0, fl1, fl2, fl3;
        upk2(fA, fl0, fl1); upk2(fB, fl2, fl3);
        float tD = ui_c * su;
        float t0 = ui_c * fl0, t1 = ui_c * fl1, t2 = ui_c * fl2, t3 = ui_c * fl3;
#pragma unroll
        for (int o = 1; o <= 8; o <<= 1) {
            tD += __shfl_xor_sync(FULLM, tD, o);
            t0 += __shfl_xor_sync(FULLM, t0, o);
            t1 += __shfl_xor_sync(FULLM, t1, o);
            t2 += __shfl_xor_sync(FULLM, t2, o);
            t3 += __shfl_xor_sync(FULLM, t3, o);
        }

        float dn = an_c - tD;
        float rd = fast_rcp(dn);
        float wi = (vi_c - su) * rd;
        float zn0 = yv_c.x - t0, zn1 = yv_c.y - t1;
        float zn2 = yv_c.z - t2, zn3 = yv_c.w - t3;

        bool pr = (t >= w0) && (t < len);
        if (pr) *pgW = wi;
        if (pr && il == 0)
            *(float4*)pgz = make_float4(zn0 * rd, zn1 * rd, zn2 * rd, zn3 * rd);
        llogd += pr ? __logf(dn) : 0.f;

        // rank-1 update: S += dn * w w^T
        float wj[16];
#pragma unroll
        for (int j = 0; j < 16; j++) wj[j] = __shfl_sync(FULLM, wi, b16 + j);
        float dwv = dn * wi;
        u64t dwP = pk2(dwv, dwv);
#pragma unroll
        for (int k = 0; k < 8; k++)
            S8[k] = fma2(dwP, pk2(wj[2*k], wj[2*k+1]), S8[k]);

        wprevP = pk2(wi, wi);
        zpA = pk2(zn0, zn1);
        zpB = pk2(zn2, zn3);
        pgW += d16; pgz += d4;
    }

    if (active && il == 0) g_logd[chunk] = llogd;
}

// ---------------------------------------------------------------------------
// Kernel 2: backward solve. 2 chunks/warp (lane halves); mid-loop reload.
// ---------------------------------------------------------------------------
__global__ void __launch_bounds__(256, 4)
backward_kernel(const float* __restrict__ U, const float* __restrict__ P,
                const float* __restrict__ y, float* __restrict__ xout,
                int N, int C, int L)
{
    int warp = (blockIdx.x * blockDim.x + threadIdx.x) >> 5;
    int lane = threadIdx.x & 31;
    int il  = lane & 15;
    int half = lane >> 4;

    int chunk = 2 * warp + half;
    bool active = (chunk < C) && ((size_t)chunk * L < (size_t)N);
    int s = active ? chunk * L : 0;
    int e = min(s + L, N);

    float g0 = 0.f, g1 = 0.f, g2 = 0.f, g3 = 0.f;
    float acc0 = 0.f, acc1 = 0.f, acc2 = 0.f, acc3 = 0.f;

    if (active && e == N) {   // last chunk: x[N-1] = z[N-1]
        float4 z2 = *(const float4*)(g_z + (size_t)(N - 1) * RDIM);
        float4 yq = *(const float4*)(y + (size_t)(N - 1) * RDIM);
        if (il == 0) *(float4*)(xout + (size_t)(N - 1) * RDIM) = z2;
        acc0 = yq.x * z2.x; acc1 = yq.y * z2.y;
        acc2 = yq.z * z2.z; acc3 = yq.w * z2.w;
    }

    int n_start = min(e - 1 + OV, N - 2);
    int len = active ? max(0, n_start - s + 1) : 0;
    int w0 = max(0, n_start - e + 1);      // first stored iteration
    int T = max(len, __shfl_xor_sync(FULLM, len, 16));

    int row = (len > 0) ? n_start : 0;
    const float* pPi = P + (size_t)row * JDIM + il;
    const float* pUi = U + (size_t)(row + 1) * JDIM + il;
    const float* pz1 = g_z + (size_t)(row + 1) * RDIM;
    const float* pW  = g_W + (size_t)row * JDIM + il;
    const float* pzn = g_z + (size_t)row * RDIM;
    const float* pY  = y + (size_t)row * RDIM;
    float*       pX  = xout + (size_t)row * RDIM;

    // preload first iteration
    float  pi = *pPi;
    float  u1 = *pUi;
    float4 z1 = *(const float4*)pz1;
    float  wi = *pW;
    float4 zn = *(const float4*)pzn;
    float4 yq = *(const float4*)pY;

#pragma unroll 1
    for (int t = 0; t < T; t++) {
        // G recurrence (consumes pi, u1, z1)
        g0 = pi * (g0 + u1 * z1.x);
        g1 = pi * (g1 + u1 * z1.y);
        g2 = pi * (g2 + u1 * z1.z);
        g3 = pi * (g3 + u1 * z1.w);

        float wi_c = wi;
        float4 zn_c = zn, yq_c = yq;

        // ---- mid-loop reload for next iteration (frozen on tail) ----
        bool adv = (t + 1 < len);
        int d16 = adv ? JDIM : 0;
        int d4  = adv ? RDIM : 0;
        pPi -= d16; pUi -= d16; pW -= d16;
        pz1 -= d4; pzn -= d4; pY -= d4;
        pi = *pPi; u1 = *pUi; z1 = *(const float4*)pz1;
        wi = *pW;  zn = *(const float4*)pzn; yq = *(const float4*)pY;
        // -------------------------------------------------------------

        float t0 = wi_c * g0, t1 = wi_c * g1, t2 = wi_c * g2, t3 = wi_c * g3;
#pragma unroll
        for (int o = 1; o <= 8; o <<= 1) {
            t0 += __shfl_xor_sync(FULLM, t0, o);
            t1 += __shfl_xor_sync(FULLM, t1, o);
            t2 += __shfl_xor_sync(FULLM, t2, o);
            t3 += __shfl_xor_sync(FULLM, t3, o);
        }

        float x0 = zn_c.x - t0, x1 = zn_c.y - t1;
        float x2 = zn_c.z - t2, x3 = zn_c.w - t3;

        bool pr = (t >= w0) && (t < len);
        if (pr && il == 0) *(float4*)pX = make_float4(x0, x1, x2, x3);
        acc0 += pr ? yq_c.x * x0 : 0.f;
        acc1 += pr ? yq_c.y * x1 : 0.f;
        acc2 += pr ? yq_c.z * x2 : 0.f;
        acc3 += pr ? yq_c.w * x3 : 0.f;
        pX -= d4;
    }

    if (active && il == 0)
        *(float4*)(g_yx + (size_t)chunk * RDIM) = make_float4(acc0, acc1, acc2, acc3);
}

// ---------------------------------------------------------------------------
// Kernel 3: finalize loglike (parallel, deterministic).
// ---------------------------------------------------------------------------
__global__ void finalize_kernel(float* __restrict__ out, int N, int Cf, int Cb)
{
    int wq = threadIdx.x >> 5;
    int lane = threadIdx.x & 31;

    double sl = 0.0;
    for (int c = lane; c < Cf; c += 32) sl += (double)g_logd[c];
#pragma unroll
    for (int o = 16; o > 0; o >>= 1) sl += __shfl_xor_sync(FULLM, sl, o);
    double norm = -0.5 * (sl + (double)N * log(6.283185307179586));

    double syx = 0.0;
    for (int c = lane; c < Cb; c += 32) syx += (double)g_yx[c * RDIM + wq];
#pragma unroll
    for (int o = 16; o > 0; o >>= 1) syx += __shfl_xor_sync(FULLM, syx, o);

    if (lane == 0 && wq < RDIM)
        out[(size_t)N * RDIM + wq] = (float)(norm - 0.5 * syx);
}

// ---------------------------------------------------------------------------
extern "C" void kernel_launch(void* const* d_in, const int* in_sizes, int n_in,
                              void* d_out, int out_size)
{
    const float* a = (const float*)d_in[0];
    const float* U = (const float*)d_in[1];
    const float* V = (const float*)d_in[2];
    const float* P = (const float*)d_in[3];
    const float* y = (const float*)d_in[4];
    float* out = (float*)d_out;

    int N = in_sizes[0];

    // forward: ~3552 warps x 2 chunks = ~7104 chunks (24 warps/SM)
    int ctF = 7104;
    int Lf = (N + ctF - 1) / ctF; if (Lf < 1) Lf = 1;
    int Cf = (N + Lf - 1) / Lf;
    if (Cf > MAXC) { Lf = (N + MAXC - 1) / MAXC; Cf = (N + Lf - 1) / Lf; }
    int warpsF = (Cf + 1) / 2;
    int blocksF = (warpsF * 32 + 255) / 256;

    // backward: ~4736 warps x 2 chunks = ~9472 chunks (32 warps/SM)
    int ctB = 9472;
    int Lb = (N + ctB - 1) / ctB; if (Lb < 1) Lb = 1;
    int Cb = (N + Lb - 1) / Lb;
    if (Cb > MAXC) { Lb = (N + MAXC - 1) / MAXC; Cb = (N + Lb - 1) / Lb; }
    int warpsB = (Cb + 1) / 2;
    int blocksB = (warpsB * 32 + 255) / 256;

    factor_forward_kernel<<<blocksF, 256>>>(a, U, V, P, y, N, Cf, Lf);
    backward_kernel<<<blocksB, 256>>>(U, P, y, out, N, Cb, Lb);
    finalize_kernel<<<1, 128>>>(out, N, Cf, Cb);
}

// round 13
// speedup vs baseline: 2.4816x; 2.4816x over previous
#include <cuda_runtime.h>
#include <cstdint>

// celerite GP factor + solve + loglike. N=262144, J=16, R=4.
// Lane-split layout: 16 lanes per chunk, TWO chunks per warp (lane halves),
// every warp instruction covers 2 sequence rows. Lane i holds the full
// S row i (8 packed f32x2 regs) and F[i][0..4). OV warm-up.
// Backward: distance-1 prefetch at occupancy 3 (reg headroom, no spill).

#define JDIM 16
#define RDIM 4
#define OV   8
#define NMAX 262144
#define MAXC 16384
#define FULLM 0xffffffffu

typedef unsigned long long u64t;

__device__ float g_W[(size_t)NMAX * JDIM];
__device__ float g_z[(size_t)NMAX * RDIM];
__device__ float g_logd[MAXC];
__device__ float g_yx[MAXC * RDIM];

__device__ __forceinline__ float fast_rcp(float x) {
    float r;
    asm("rcp.approx.f32 %0, %1;" : "=f"(r) : "f"(x));
    r = r * (2.0f - x * r);
    return r;
}
__device__ __forceinline__ u64t pk2(float lo, float hi) {
    u64t r; asm("mov.b64 %0, {%1,%2};" : "=l"(r) : "f"(lo), "f"(hi)); return r;
}
__device__ __forceinline__ void upk2(u64t v, float& lo, float& hi) {
    asm("mov.b64 {%0,%1}, %2;" : "=f"(lo), "=f"(hi) : "l"(v));
}
__device__ __forceinline__ u64t mul2(u64t a, u64t b) {
    u64t r; asm("mul.rn.f32x2 %0, %1, %2;" : "=l"(r) : "l"(a), "l"(b)); return r;
}
__device__ __forceinline__ u64t add2(u64t a, u64t b) {
    u64t r; asm("add.rn.f32x2 %0, %1, %2;" : "=l"(r) : "l"(a), "l"(b)); return r;
}
__device__ __forceinline__ u64t fma2(u64t a, u64t b, u64t c) {
    u64t r; asm("fma.rn.f32x2 %0, %1, %2, %3;" : "=l"(r) : "l"(a), "l"(b), "l"(c)); return r;
}

// ---------------------------------------------------------------------------
// Kernel 1: fused factorization + forward solve. 2 chunks/warp (lane halves).
// (R11 structure verbatim — loads at loop top, no saved copies.)
// ---------------------------------------------------------------------------
__global__ void __launch_bounds__(256, 3)
factor_forward_kernel(const float* __restrict__ a, const float* __restrict__ U,
                      const float* __restrict__ V, const float* __restrict__ P,
                      const float* __restrict__ y, int N, int C, int L)
{
    int warp = (blockIdx.x * blockDim.x + threadIdx.x) >> 5;
    int lane = threadIdx.x & 31;
    int il  = lane & 15;
    int b16 = lane & 16;
    int half = lane >> 4;

    int chunk = 2 * warp + half;
    bool active = (chunk < C) && ((size_t)chunk * L < (size_t)N);
    int s = active ? chunk * L : 0;
    int e = min(s + L, N);
    int m0 = max(0, s - OV);
    int len = active ? (e - m0 - 1) : 0;
    int T = max(len, __shfl_xor_sync(FULLM, len, 16));

    // ---- init at row m0
    u64t S8[8];
    u64t fA, fB, zpA, zpB, wprevP;
    float llogd = 0.f;
    {
        float an = a[m0];
        float vi = V[(size_t)m0 * JDIM + il];
        float rd = fast_rcp(an);
        float wi = vi * rd;
        float wj[16];
#pragma unroll
        for (int j = 0; j < 16; j++) wj[j] = __shfl_sync(FULLM, wi, b16 + j);
        float dw = an * wi;
#pragma unroll
        for (int k = 0; k < 8; k++) S8[k] = pk2(dw * wj[2*k], dw * wj[2*k+1]);

        float4 y0 = *(const float4*)(y + (size_t)m0 * RDIM);
        zpA = pk2(y0.x, y0.y);
        zpB = pk2(y0.z, y0.w);
        fA = 0ull; fB = 0ull;
        wprevP = pk2(wi, wi);

        if (active && m0 == s) {   // chunk 0: store row 0
            g_W[(size_t)m0 * JDIM + il] = wi;
            if (il == 0) *(float4*)(g_z + (size_t)m0 * RDIM) =
                make_float4(y0.x * rd, y0.y * rd, y0.z * rd, y0.w * rd);
            llogd = __logf(an);
        }
    }

    // ---- pointers at first loop row n = m0+1 (P uses row n-1)
    int r1 = m0 + 1;
    const float* pP  = P + (size_t)m0 * JDIM;
    const float* pPi = pP + il;
    const float* pU  = U + (size_t)r1 * JDIM;
    const float* pUi = pU + il;
    const float* pVi = V + (size_t)r1 * JDIM + il;
    const float* pa  = a + r1;
    const float* pY  = y + (size_t)r1 * RDIM;
    float* pgW = g_W + (size_t)r1 * JDIM + il;
    float* pgz = g_z + (size_t)r1 * RDIM;
    int nrow = r1;

#pragma unroll 1
    for (int t = 0; t < T; t++) {
        // loads (full rows broadcast within half; scalars per lane)
        ulonglong2 pjA = *(const ulonglong2*)(pP);
        ulonglong2 pjB = *(const ulonglong2*)(pP + 4);
        ulonglong2 pjC = *(const ulonglong2*)(pP + 8);
        ulonglong2 pjD = *(const ulonglong2*)(pP + 12);
        float pi = *pPi;
        ulonglong2 ujA = *(const ulonglong2*)(pU);
        ulonglong2 ujB = *(const ulonglong2*)(pU + 4);
        ulonglong2 ujC = *(const ulonglong2*)(pU + 8);
        ulonglong2 ujD = *(const ulonglong2*)(pU + 12);
        float ui = *pUi;
        float vi = *pVi;
        float an = *pa;
        float4 yv = *(const float4*)(pY);

        u64t pis = pk2(pi, pi);

        // F recurrence
        fA = mul2(pis, fma2(wprevP, zpA, fA));
        fB = mul2(pis, fma2(wprevP, zpB, fB));

        // S decay (row i scaled by pi * pj elementwise)
        S8[0] = mul2(S8[0], mul2(pis, pjA.x));
        S8[1] = mul2(S8[1], mul2(pis, pjA.y));
        S8[2] = mul2(S8[2], mul2(pis, pjB.x));
        S8[3] = mul2(S8[3], mul2(pis, pjB.y));
        S8[4] = mul2(S8[4], mul2(pis, pjC.x));
        S8[5] = mul2(S8[5], mul2(pis, pjC.y));
        S8[6] = mul2(S8[6], mul2(pis, pjD.x));
        S8[7] = mul2(S8[7], mul2(pis, pjD.y));

        // su_i = S row . U row  (fully lane-local)
        u64t q0 = mul2(S8[0], ujA.x), q1 = mul2(S8[1], ujA.y);
        u64t q2 = mul2(S8[2], ujB.x), q3 = mul2(S8[3], ujB.y);
        u64t q4 = mul2(S8[4], ujC.x), q5 = mul2(S8[5], ujC.y);
        u64t q6 = mul2(S8[6], ujD.x), q7 = mul2(S8[7], ujD.y);
        u64t qa = add2(add2(q0, q1), add2(q2, q3));
        u64t qb = add2(add2(q4, q5), add2(q6, q7));
        u64t qt = add2(qa, qb);
        float qlo, qhi; upk2(qt, qlo, qhi);
        float su = qlo + qhi;

        // reductions over the 16-lane half: tD = U.SU, t0..t3 = U.F
        float fl0, fl1, fl2, fl3;
        upk2(fA, fl0, fl1); upk2(fB, fl2, fl3);
        float tD = ui * su;
        float t0 = ui * fl0, t1 = ui * fl1, t2 = ui * fl2, t3 = ui * fl3;
#pragma unroll
        for (int o = 1; o <= 8; o <<= 1) {
            tD += __shfl_xor_sync(FULLM, tD, o);
            t0 += __shfl_xor_sync(FULLM, t0, o);
            t1 += __shfl_xor_sync(FULLM, t1, o);
            t2 += __shfl_xor_sync(FULLM, t2, o);
            t3 += __shfl_xor_sync(FULLM, t3, o);
        }

        float dn = an - tD;
        float rd = fast_rcp(dn);
        float wi = (vi - su) * rd;
        float zn0 = yv.x - t0, zn1 = yv.y - t1;
        float zn2 = yv.z - t2, zn3 = yv.w - t3;

        bool pr = (t < len) && (nrow >= s);
        if (pr) *pgW = wi;
        if (pr && il == 0)
            *(float4*)pgz = make_float4(zn0 * rd, zn1 * rd, zn2 * rd, zn3 * rd);
        llogd += pr ? __logf(dn) : 0.f;

        // rank-1 update: S += dn * w w^T
        float wj[16];
#pragma unroll
        for (int j = 0; j < 16; j++) wj[j] = __shfl_sync(FULLM, wi, b16 + j);
        float dwv = dn * wi;
        u64t dwP = pk2(dwv, dwv);
#pragma unroll
        for (int k = 0; k < 8; k++)
            S8[k] = fma2(dwP, pk2(wj[2*k], wj[2*k+1]), S8[k]);

        wprevP = pk2(wi, wi);
        zpA = pk2(zn0, zn1);
        zpB = pk2(zn2, zn3);

        // predicated pointer advance (freeze on tail)
        bool adv = (t + 1 < len);
        int d16 = adv ? JDIM : 0;
        int d4  = adv ? RDIM : 0;
        int d1  = adv ? 1 : 0;
        pP += d16; pPi += d16; pU += d16; pUi += d16; pVi += d16;
        pa += d1; pY += d4; pgW += d16; pgz += d4; nrow += d1;
    }

    if (active && il == 0) g_logd[chunk] = llogd;
}

// ---------------------------------------------------------------------------
// Kernel 2: backward solve. 2 chunks/warp (lane halves).
// Distance-1 prefetch at occupancy 3 (85-reg cap gives spill headroom).
// ---------------------------------------------------------------------------
__global__ void __launch_bounds__(256, 3)
backward_kernel(const float* __restrict__ U, const float* __restrict__ P,
                const float* __restrict__ y, float* __restrict__ xout,
                int N, int C, int L)
{
    int warp = (blockIdx.x * blockDim.x + threadIdx.x) >> 5;
    int lane = threadIdx.x & 31;
    int il  = lane & 15;
    int half = lane >> 4;

    int chunk = 2 * warp + half;
    bool active = (chunk < C) && ((size_t)chunk * L < (size_t)N);
    int s = active ? chunk * L : 0;
    int e = min(s + L, N);

    float g0 = 0.f, g1 = 0.f, g2 = 0.f, g3 = 0.f;
    float acc0 = 0.f, acc1 = 0.f, acc2 = 0.f, acc3 = 0.f;

    if (active && e == N) {   // last chunk: x[N-1] = z[N-1]
        float4 z2 = *(const float4*)(g_z + (size_t)(N - 1) * RDIM);
        float4 yq = *(const float4*)(y + (size_t)(N - 1) * RDIM);
        if (il == 0) *(float4*)(xout + (size_t)(N - 1) * RDIM) = z2;
        acc0 = yq.x * z2.x; acc1 = yq.y * z2.y;
        acc2 = yq.z * z2.z; acc3 = yq.w * z2.w;
    }

    int n_start = min(e - 1 + OV, N - 2);
    int len = active ? max(0, n_start - s + 1) : 0;
    int w0 = max(0, n_start - e + 1);      // first stored iteration
    int T = max(len, __shfl_xor_sync(FULLM, len, 16));

    int row = (len > 0) ? n_start : 0;
    const float* pPi = P + (size_t)row * JDIM + il;
    const float* pUi = U + (size_t)(row + 1) * JDIM + il;
    const float* pz1 = g_z + (size_t)(row + 1) * RDIM;
    const float* pW  = g_W + (size_t)row * JDIM + il;
    const float* pzn = g_z + (size_t)row * RDIM;
    const float* pY  = y + (size_t)row * RDIM;
    float*       pX  = xout + (size_t)row * RDIM;

    // preload iteration 0
    float  pi = *pPi;
    float  u1 = *pUi;
    float4 z1 = *(const float4*)pz1;
    float  wi = *pW;
    float4 zn = *(const float4*)pzn;
    float4 yq = *(const float4*)pY;

#pragma unroll 1
    for (int t = 0; t < T; t++) {
        float cpi = pi, cu1 = u1, cwi = wi;
        float4 cz1 = z1, czn = zn, cyq = yq;

        // prefetch next iteration (frozen on tail)
        bool adv = (t + 1 < len);
        int d16 = adv ? JDIM : 0;
        int d4  = adv ? RDIM : 0;
        pPi -= d16; pUi -= d16; pW -= d16;
        pz1 -= d4; pzn -= d4; pY -= d4;
        pi = *pPi; u1 = *pUi; z1 = *(const float4*)pz1;
        wi = *pW;  zn = *(const float4*)pzn; yq = *(const float4*)pY;

        // G recurrence
        g0 = cpi * (g0 + cu1 * cz1.x);
        g1 = cpi * (g1 + cu1 * cz1.y);
        g2 = cpi * (g2 + cu1 * cz1.z);
        g3 = cpi * (g3 + cu1 * cz1.w);

        float t0 = cwi * g0, t1 = cwi * g1, t2 = cwi * g2, t3 = cwi * g3;
#pragma unroll
        for (int o = 1; o <= 8; o <<= 1) {
            t0 += __shfl_xor_sync(FULLM, t0, o);
            t1 += __shfl_xor_sync(FULLM, t1, o);
            t2 += __shfl_xor_sync(FULLM, t2, o);
            t3 += __shfl_xor_sync(FULLM, t3, o);
        }

        float x0 = czn.x - t0, x1 = czn.y - t1;
        float x2 = czn.z - t2, x3 = czn.w - t3;

        bool pr = (t >= w0) && (t < len);
        if (pr && il == 0) *(float4*)pX = make_float4(x0, x1, x2, x3);
        acc0 += pr ? cyq.x * x0 : 0.f;
        acc1 += pr ? cyq.y * x1 : 0.f;
        acc2 += pr ? cyq.z * x2 : 0.f;
        acc3 += pr ? cyq.w * x3 : 0.f;
        pX -= d4;
    }

    if (active && il == 0)
        *(float4*)(g_yx + (size_t)chunk * RDIM) = make_float4(acc0, acc1, acc2, acc3);
}

// ---------------------------------------------------------------------------
// Kernel 3: finalize loglike (parallel, deterministic).
// ---------------------------------------------------------------------------
__global__ void finalize_kernel(float* __restrict__ out, int N, int Cf, int Cb)
{
    int wq = threadIdx.x >> 5;
    int lane = threadIdx.x & 31;

    double sl = 0.0;
    for (int c = lane; c < Cf; c += 32) sl += (double)g_logd[c];
#pragma unroll
    for (int o = 16; o > 0; o >>= 1) sl += __shfl_xor_sync(FULLM, sl, o);
    double norm = -0.5 * (sl + (double)N * log(6.283185307179586));

    double syx = 0.0;
    for (int c = lane; c < Cb; c += 32) syx += (double)g_yx[c * RDIM + wq];
#pragma unroll
    for (int o = 16; o > 0; o >>= 1) syx += __shfl_xor_sync(FULLM, syx, o);

    if (lane == 0 && wq < RDIM)
        out[(size_t)N * RDIM + wq] = (float)(norm - 0.5 * syx);
}

// ---------------------------------------------------------------------------
extern "C" void kernel_launch(void* const* d_in, const int* in_sizes, int n_in,
                              void* d_out, int out_size)
{
    const float* a = (const float*)d_in[0];
    const float* U = (const float*)d_in[1];
    const float* V = (const float*)d_in[2];
    const float* P = (const float*)d_in[3];
    const float* y = (const float*)d_in[4];
    float* out = (float*)d_out;

    int N = in_sizes[0];

    // forward: ~3552 warps x 2 chunks = ~7104 chunks (24 warps/SM)
    int ctF = 7104;
    int Lf = (N + ctF - 1) / ctF; if (Lf < 1) Lf = 1;
    int Cf = (N + Lf - 1) / Lf;
    if (Cf > MAXC) { Lf = (N + MAXC - 1) / MAXC; Cf = (N + Lf - 1) / Lf; }
    int warpsF = (Cf + 1) / 2;
    int blocksF = (warpsF * 32 + 255) / 256;

    // backward: ~3552 warps x 2 chunks = ~7104 chunks (24 warps/SM, occ 3)
    int ctB = 7104;
    int Lb = (N + ctB - 1) / ctB; if (Lb < 1) Lb = 1;
    int Cb = (N + Lb - 1) / Lb;
    if (Cb > MAXC) { Lb = (N + MAXC - 1) / MAXC; Cb = (N + Lb - 1) / Lb; }
    int warpsB = (Cb + 1) / 2;
    int blocksB = (warpsB * 32 + 255) / 256;

    factor_forward_kernel<<<blocksF, 256>>>(a, U, V, P, y, N, Cf, Lf);
    backward_kernel<<<blocksB, 256>>>(U, P, y, out, N, Cb, Lb);
    finalize_kernel<<<1, 128>>>(out, N, Cf, Cb);
}